// round 10
// baseline (speedup 1.0000x reference)
#include <cuda_runtime.h>
#include <cuda_bf16.h>
#include <cuda_fp16.h>

// Problem constants (fixed by the dataset).
#define NMAX 50000
#define CAP  64           // max in-degree bucket (Poisson mean 25; P(>64)~e-107)
#define DH   64
#define BGR  512

// ---------------- scratch (static device memory; no allocations) -----------
__device__ int     g_cnt [NMAX];                  // in-degree (excl. self loop)
__device__ int     g_csr [(size_t)NMAX * CAP];    // bucketed incoming src lists
__device__ __half2 g_h1  [(size_t)NMAX * 32];     // layer outputs (ping, fp16)
__device__ __half2 g_h2  [(size_t)NMAX * 32];     // layer outputs (pong, fp16)
__device__ __half2 g_g   [(size_t)NMAX * 32];     // dinv-scaled GEMM output
__device__ float   g_pool[BGR * DH];              // per-graph feature sums
__device__ int     g_pcnt[BGR];                   // per-graph node counts

// ---------------- setup kernels --------------------------------------------
__global__ void zero_kernel(int n) {
    int i = blockIdx.x * blockDim.x + threadIdx.x;
    if (i < n)        g_cnt[i]  = 0;
    if (i < BGR * DH) g_pool[i] = 0.0f;
    if (i < BGR)      g_pcnt[i] = 0;
}

__global__ void csr_build_kernel(const int* __restrict__ ei, int e_count) {
    int e = blockIdx.x * blockDim.x + threadIdx.x;
    if (e >= e_count) return;
    int src = ei[e];
    int dst = ei[e_count + e];
    int slot = atomicAdd(&g_cnt[dst], 1);
    if (slot < CAP) g_csr[(size_t)dst * CAP + slot] = src;
}

// batch sorted -> warp-aggregated atomics (1-2 distinct b per warp).
// Runs as a SEPARATE launch after zero_kernel (g_pcnt init must be ordered
// before these atomics — fusing them raced and corrupted the pool divisors).
__global__ void pcnt_kernel(const int* __restrict__ batch, int n) {
    int i = blockIdx.x * blockDim.x + threadIdx.x;
    if (i >= n) return;
    int b = batch[i];
    unsigned mask = __match_any_sync(__activemask(), b);
    int leader = __ffs(mask) - 1;
    if ((int)(threadIdx.x & 31) == leader)
        atomicAdd(&g_pcnt[b], __popc(mask));
}

// ---------------- GEMM via mma.sync.m16n8k16 (fp16 in, fp32 acc) -----------
// out[r][c] = rsqrt(deg[r]+1) * sum_k hin[r][k] * W[c][k], fp16 to g_g.
// N-split: each warp handles one 16-row tile x 32-column half (2 warps/tile).
__global__ __launch_bounds__(256) void gemm_mma_kernel(
    const float* __restrict__ x_ext, int which, const float* __restrict__ W,
    int n)
{
    const __half2* hin = (which == 1) ? g_h1 : g_h2;

    __shared__ unsigned bs[2048];      // 8 KB of B fragments (all 64 cols)

    int tid = threadIdx.x;
#pragma unroll
    for (int i = 0; i < 8; i++) {
        int flat = tid + i * 256;          // [0,2048)
        int kc =  flat >> 9;
        int nt = (flat >> 6) & 7;
        int gg = (flat >> 3) & 7;
        int tt = (flat >> 1) & 3;
        int j  =  flat & 1;
        int col = nt * 8 + gg;
        int k   = kc * 16 + 2 * tt + 8 * j;
        __half2 h = __floats2half2_rn(W[col * 64 + k], W[col * 64 + k + 1]);
        bs[flat] = *(unsigned*)&h;
    }
    __syncthreads();

    int lane = tid & 31;
    int g = lane >> 2, t = lane & 3;

    int job_id  = (blockIdx.x * blockDim.x + tid) >> 5;
    int njobs   = (gridDim.x * blockDim.x) >> 5;
    int ntiles  = (n + 15) >> 4;
    int totjobs = ntiles * 2;

    for (int job = job_id; job < totjobs; job += njobs) {
        int rt   = job >> 1;
        int half = job & 1;            // n-half: cols [32*half, 32*half+32)
        int row0 = rt * 16;
        int r_lo = row0 + g;
        int r_hi = row0 + g + 8;
        bool ok_lo = (r_lo < n), ok_hi = (r_hi < n);

        unsigned a[4][4];
        if (which == 0) {
            const float* plo = x_ext + (size_t)r_lo * 64;
            const float* phi = x_ext + (size_t)r_hi * 64;
#pragma unroll
            for (int kc = 0; kc < 4; kc++) {
                int k0 = kc * 16 + 2 * t;
                if (ok_lo) {
                    float2 v0 = *(const float2*)&plo[k0];
                    float2 v1 = *(const float2*)&plo[k0 + 8];
                    __half2 q0 = __floats2half2_rn(v0.x, v0.y);
                    __half2 q1 = __floats2half2_rn(v1.x, v1.y);
                    a[kc][0] = *(unsigned*)&q0; a[kc][2] = *(unsigned*)&q1;
                } else { a[kc][0] = 0u; a[kc][2] = 0u; }
                if (ok_hi) {
                    float2 v0 = *(const float2*)&phi[k0];
                    float2 v1 = *(const float2*)&phi[k0 + 8];
                    __half2 q0 = __floats2half2_rn(v0.x, v0.y);
                    __half2 q1 = __floats2half2_rn(v1.x, v1.y);
                    a[kc][1] = *(unsigned*)&q0; a[kc][3] = *(unsigned*)&q1;
                } else { a[kc][1] = 0u; a[kc][3] = 0u; }
            }
        } else {
            const __half2* plo = hin + (size_t)r_lo * 32;
            const __half2* phi = hin + (size_t)r_hi * 32;
#pragma unroll
            for (int kc = 0; kc < 4; kc++) {
                if (ok_lo) {
                    a[kc][0] = *(const unsigned*)&plo[kc * 8 + t];
                    a[kc][2] = *(const unsigned*)&plo[kc * 8 + t + 4];
                } else { a[kc][0] = 0u; a[kc][2] = 0u; }
                if (ok_hi) {
                    a[kc][1] = *(const unsigned*)&phi[kc * 8 + t];
                    a[kc][3] = *(const unsigned*)&phi[kc * 8 + t + 4];
                } else { a[kc][1] = 0u; a[kc][3] = 0u; }
            }
        }

        float c[4][4];
#pragma unroll
        for (int q = 0; q < 4; q++) { c[q][0]=0.f; c[q][1]=0.f; c[q][2]=0.f; c[q][3]=0.f; }

        int ntbase = half * 4;
#pragma unroll
        for (int kc = 0; kc < 4; kc++)
#pragma unroll
            for (int q = 0; q < 4; q++) {
                int nt = ntbase + q;
                uint2 bb = *(const uint2*)&bs[(((kc * 8 + nt) * 8 + g) * 4 + t) * 2];
                asm volatile(
                    "mma.sync.aligned.m16n8k16.row.col.f32.f16.f16.f32 "
                    "{%0,%1,%2,%3}, {%4,%5,%6,%7}, {%8,%9}, {%0,%1,%2,%3};"
                    : "+f"(c[q][0]), "+f"(c[q][1]), "+f"(c[q][2]), "+f"(c[q][3])
                    : "r"(a[kc][0]), "r"(a[kc][1]), "r"(a[kc][2]), "r"(a[kc][3]),
                      "r"(bb.x), "r"(bb.y));
            }

        if (ok_lo) {
            float dlo = rsqrtf((float)g_cnt[r_lo] + 1.0f);
            __half2* olo = g_g + (size_t)r_lo * 32;
#pragma unroll
            for (int q = 0; q < 4; q++)
                olo[(ntbase + q) * 4 + t] = __floats2half2_rn(c[q][0] * dlo, c[q][1] * dlo);
        }
        if (ok_hi) {
            float dhi = rsqrtf((float)g_cnt[r_hi] + 1.0f);
            __half2* ohi = g_g + (size_t)r_hi * 32;
#pragma unroll
            for (int q = 0; q < 4; q++)
                ohi[(ntbase + q) * 4 + t] = __floats2half2_rn(c[q][2] * dhi, c[q][3] * dhi);
        }
    }
}

// ---------------- aggregation: one warp per destination node ----------------
// acc = g[i] (self loop) + sum over incoming srcs of g[src]   (g is fp16)
// Main loop holds 16 independent gathers in flight (MLP=16).
__global__ __launch_bounds__(512) void agg_kernel(
    const float* __restrict__ bias,
    const int*   __restrict__ batch,
    int mode, int n)
{
    int w = (blockIdx.x * blockDim.x + threadIdx.x) >> 5;
    if (w >= n) return;
    int lane = threadIdx.x & 31;
    int c0 = lane * 2;

    float2 acc = __half22float2(g_g[(size_t)w * 32 + lane]);  // self loop
    float2 acc2 = make_float2(0.f, 0.f);

    int cnt  = g_cnt[w];
    int cnum = min(cnt, CAP);
    const int* lst = &g_csr[(size_t)w * CAP];

    int e = 0;
    for (; e + 16 <= cnum; e += 16) {
        int4 sa = *(const int4*)&lst[e];                      // uniform broadcast
        int4 sb = *(const int4*)&lst[e + 4];
        int4 sc = *(const int4*)&lst[e + 8];
        int4 sd = *(const int4*)&lst[e + 12];
        float2 v0 = __half22float2(g_g[(size_t)sa.x * 32 + lane]);
        float2 v1 = __half22float2(g_g[(size_t)sa.y * 32 + lane]);
        float2 v2 = __half22float2(g_g[(size_t)sa.z * 32 + lane]);
        float2 v3 = __half22float2(g_g[(size_t)sa.w * 32 + lane]);
        float2 v4 = __half22float2(g_g[(size_t)sb.x * 32 + lane]);
        float2 v5 = __half22float2(g_g[(size_t)sb.y * 32 + lane]);
        float2 v6 = __half22float2(g_g[(size_t)sb.z * 32 + lane]);
        float2 v7 = __half22float2(g_g[(size_t)sb.w * 32 + lane]);
        float2 v8 = __half22float2(g_g[(size_t)sc.x * 32 + lane]);
        float2 v9 = __half22float2(g_g[(size_t)sc.y * 32 + lane]);
        float2 va = __half22float2(g_g[(size_t)sc.z * 32 + lane]);
        float2 vb = __half22float2(g_g[(size_t)sc.w * 32 + lane]);
        float2 vc = __half22float2(g_g[(size_t)sd.x * 32 + lane]);
        float2 vd = __half22float2(g_g[(size_t)sd.y * 32 + lane]);
        float2 ve = __half22float2(g_g[(size_t)sd.z * 32 + lane]);
        float2 vf = __half22float2(g_g[(size_t)sd.w * 32 + lane]);
        acc.x  += ((v0.x + v1.x) + (v2.x + v3.x)) + ((v4.x + v5.x) + (v6.x + v7.x));
        acc.y  += ((v0.y + v1.y) + (v2.y + v3.y)) + ((v4.y + v5.y) + (v6.y + v7.y));
        acc2.x += ((v8.x + v9.x) + (va.x + vb.x)) + ((vc.x + vd.x) + (ve.x + vf.x));
        acc2.y += ((v8.y + v9.y) + (va.y + vb.y)) + ((vc.y + vd.y) + (ve.y + vf.y));
    }
    for (; e + 8 <= cnum; e += 8) {
        int4 sa = *(const int4*)&lst[e];
        int4 sb = *(const int4*)&lst[e + 4];
        float2 v0 = __half22float2(g_g[(size_t)sa.x * 32 + lane]);
        float2 v1 = __half22float2(g_g[(size_t)sa.y * 32 + lane]);
        float2 v2 = __half22float2(g_g[(size_t)sa.z * 32 + lane]);
        float2 v3 = __half22float2(g_g[(size_t)sa.w * 32 + lane]);
        float2 v4 = __half22float2(g_g[(size_t)sb.x * 32 + lane]);
        float2 v5 = __half22float2(g_g[(size_t)sb.y * 32 + lane]);
        float2 v6 = __half22float2(g_g[(size_t)sb.z * 32 + lane]);
        float2 v7 = __half22float2(g_g[(size_t)sb.w * 32 + lane]);
        acc.x  += (v0.x + v1.x) + (v2.x + v3.x);
        acc.y  += (v0.y + v1.y) + (v2.y + v3.y);
        acc2.x += (v4.x + v5.x) + (v6.x + v7.x);
        acc2.y += (v4.y + v5.y) + (v6.y + v7.y);
    }
    for (; e + 4 <= cnum; e += 4) {
        int4 s4 = *(const int4*)&lst[e];
        float2 v0 = __half22float2(g_g[(size_t)s4.x * 32 + lane]);
        float2 v1 = __half22float2(g_g[(size_t)s4.y * 32 + lane]);
        float2 v2 = __half22float2(g_g[(size_t)s4.z * 32 + lane]);
        float2 v3 = __half22float2(g_g[(size_t)s4.w * 32 + lane]);
        acc.x += (v0.x + v1.x) + (v2.x + v3.x);
        acc.y += (v0.y + v1.y) + (v2.y + v3.y);
    }
    for (; e < cnum; e++) {
        int s = lst[e];
        float2 v = __half22float2(g_g[(size_t)s * 32 + lane]);
        acc.x += v.x;
        acc.y += v.y;
    }
    acc.x += acc2.x;
    acc.y += acc2.y;

    float dv = rsqrtf((float)cnt + 1.0f);
    float ox = fmaxf(fmaf(dv, acc.x, bias[c0    ]), 0.0f);
    float oy = fmaxf(fmaf(dv, acc.y, bias[c0 + 1]), 0.0f);

    if (mode == 1) {
        g_h1[(size_t)w * 32 + lane] = __floats2half2_rn(ox, oy);
    } else if (mode == 2) {
        g_h2[(size_t)w * 32 + lane] = __floats2half2_rn(ox, oy);
    } else {
        int b = batch[w];
        atomicAdd(&g_pool[b * 64 + c0    ], ox);
        atomicAdd(&g_pool[b * 64 + c0 + 1], oy);
    }
}

// ---------------- final: out[b][o] = mean-pool(b) . Wl[o] + bl[o] -----------
__global__ void final_kernel(const float* __restrict__ Wl,
                             const float* __restrict__ bl,
                             float* __restrict__ out)
{
    int t = blockIdx.x * blockDim.x + threadIdx.x;
    if (t >= BGR * 16) return;
    int b = t >> 4, o = t & 15;
    float inv = 1.0f / fmaxf((float)g_pcnt[b], 1.0f);
    const float* pr = &g_pool[b * 64];
    const float* wr = &Wl[o * 64];
    float s = 0.0f;
#pragma unroll
    for (int k = 0; k < 64; k++) s = fmaf(pr[k], wr[k], s);
    out[t] = fmaf(s, inv, bl[o]);
}

// ---------------- launch ----------------------------------------------------
extern "C" void kernel_launch(void* const* d_in, const int* in_sizes, int n_in,
                              void* d_out, int out_size)
{
    const float* x     = (const float*)d_in[0];
    const int*   ei    = (const int*)  d_in[1];
    const int*   batch = (const int*)  d_in[2];
    const float* W1    = (const float*)d_in[3];
    const float* b1    = (const float*)d_in[4];
    const float* W2    = (const float*)d_in[5];
    const float* b2    = (const float*)d_in[6];
    const float* W3    = (const float*)d_in[7];
    const float* b3    = (const float*)d_in[8];
    const float* Wl    = (const float*)d_in[9];
    const float* bl    = (const float*)d_in[10];
    float* out = (float*)d_out;

    int n = in_sizes[0] / 64;   // 50000
    int e = in_sizes[1] / 2;    // 1250000

    int nb_n = (n + 255) / 256;
    int nb_e = (e + 255) / 256;
    int nb_a = (n * 32 + 511) / 512;       // agg: 1 warp / node
    int njobs = ((n + 15) / 16) * 2;       // gemm: 2 warps / 16-row tile
    int nb_m = (njobs + 7) / 8;

    // Launch order: zero(1), csr(2), gemm1(3), agg1(4) <- ncu window, pcnt(5).
    // pcnt only feeds final_kernel, so deferring it past agg1 is safe; its
    // atomics are now stream-ordered AFTER zero_kernel's init (fusing raced).
    zero_kernel<<<nb_n, 256>>>(n);
    csr_build_kernel<<<nb_e, 256>>>(ei, e);

    gemm_mma_kernel<<<nb_m, 256>>>(x, 0, W1, n);
    agg_kernel<<<nb_a, 512>>>(b1, batch, 1, n);

    pcnt_kernel<<<nb_n, 256>>>(batch, n);

    gemm_mma_kernel<<<nb_m, 256>>>(x, 1, W2, n);
    agg_kernel<<<nb_a, 512>>>(b2, batch, 2, n);

    gemm_mma_kernel<<<nb_m, 256>>>(x, 2, W3, n);
    agg_kernel<<<nb_a, 512>>>(b3, batch, 3, n);

    final_kernel<<<(BGR * 16 + 255) / 256, 256>>>(Wl, bl, out);
}

// round 11
// speedup vs baseline: 1.1866x; 1.1866x over previous
#include <cuda_runtime.h>
#include <cuda_bf16.h>
#include <cuda_fp16.h>

// Problem constants (fixed by the dataset).
#define NMAX 50000
#define CAP  64           // max in-degree bucket (Poisson mean 25; P(>64)~e-107)
#define DH   64
#define BGR  512

// ---------------- scratch (static device memory; no allocations) -----------
__device__ int     g_cnt [NMAX];                  // in-degree (excl. self loop)
__device__ int     g_csr [(size_t)NMAX * CAP];    // bucketed incoming src lists
__device__ __half2 g_h1  [(size_t)NMAX * 32];     // layer outputs (ping, fp16)
__device__ __half2 g_h2  [(size_t)NMAX * 32];     // layer outputs (pong, fp16)
__device__ __half2 g_g   [(size_t)NMAX * 32];     // dinv-scaled GEMM output
__device__ float   g_pool[BGR * DH];              // per-graph feature sums
__device__ int     g_pcnt[BGR];                   // per-graph node counts

// ---------------- setup kernels --------------------------------------------
__global__ void zero_kernel(int n) {
    int i = blockIdx.x * blockDim.x + threadIdx.x;
    if (i < n)        g_cnt[i]  = 0;
    if (i < BGR * DH) g_pool[i] = 0.0f;
    if (i < BGR)      g_pcnt[i] = 0;
}

__global__ void csr_build_kernel(const int* __restrict__ ei, int e_count) {
    int e = blockIdx.x * blockDim.x + threadIdx.x;
    if (e >= e_count) return;
    int src = ei[e];
    int dst = ei[e_count + e];
    int slot = atomicAdd(&g_cnt[dst], 1);
    if (slot < CAP) g_csr[(size_t)dst * CAP + slot] = src;
}

// batch sorted -> warp-aggregated atomics. Separate launch AFTER zero_kernel
// (fusing the init and the atomics raced; deferred past agg1 for ncu window).
__global__ void pcnt_kernel(const int* __restrict__ batch, int n) {
    int i = blockIdx.x * blockDim.x + threadIdx.x;
    if (i >= n) return;
    int b = batch[i];
    unsigned mask = __match_any_sync(__activemask(), b);
    int leader = __ffs(mask) - 1;
    if ((int)(threadIdx.x & 31) == leader)
        atomicAdd(&g_pcnt[b], __popc(mask));
}

// ---------------- GEMM via mma.sync.m16n8k16 (fp16 in, fp32 acc) -----------
// out[r][c] = rsqrt(deg[r]+1) * sum_k hin[r][k] * W[c][k], fp16 to g_g.
// 1 tile (16 rows x 64 cols) per warp — best measured config (R8: 10.1us).
__global__ __launch_bounds__(256) void gemm_mma_kernel(
    const float* __restrict__ x_ext, int which, const float* __restrict__ W,
    int n)
{
    const __half2* hin = (which == 1) ? g_h1 : g_h2;

    __shared__ unsigned bs[2048];      // 8 KB of B fragments

    int tid = threadIdx.x;
#pragma unroll
    for (int i = 0; i < 8; i++) {
        int flat = tid + i * 256;          // [0,2048)
        int kc =  flat >> 9;
        int nt = (flat >> 6) & 7;
        int gg = (flat >> 3) & 7;
        int tt = (flat >> 1) & 3;
        int j  =  flat & 1;
        int col = nt * 8 + gg;
        int k   = kc * 16 + 2 * tt + 8 * j;
        __half2 h = __floats2half2_rn(W[col * 64 + k], W[col * 64 + k + 1]);
        bs[flat] = *(unsigned*)&h;
    }
    __syncthreads();

    int lane = tid & 31;
    int g = lane >> 2, t = lane & 3;

    int warp_id = (blockIdx.x * blockDim.x + tid) >> 5;
    int nwarps  = (gridDim.x * blockDim.x) >> 5;
    int ntiles  = (n + 15) >> 4;

    for (int rt = warp_id; rt < ntiles; rt += nwarps) {
        int row0 = rt * 16;
        int r_lo = row0 + g;
        int r_hi = row0 + g + 8;
        bool ok_lo = (r_lo < n), ok_hi = (r_hi < n);

        unsigned a[4][4];
        if (which == 0) {
            const float* plo = x_ext + (size_t)r_lo * 64;
            const float* phi = x_ext + (size_t)r_hi * 64;
#pragma unroll
            for (int kc = 0; kc < 4; kc++) {
                int k0 = kc * 16 + 2 * t;
                if (ok_lo) {
                    float2 v0 = *(const float2*)&plo[k0];
                    float2 v1 = *(const float2*)&plo[k0 + 8];
                    __half2 q0 = __floats2half2_rn(v0.x, v0.y);
                    __half2 q1 = __floats2half2_rn(v1.x, v1.y);
                    a[kc][0] = *(unsigned*)&q0; a[kc][2] = *(unsigned*)&q1;
                } else { a[kc][0] = 0u; a[kc][2] = 0u; }
                if (ok_hi) {
                    float2 v0 = *(const float2*)&phi[k0];
                    float2 v1 = *(const float2*)&phi[k0 + 8];
                    __half2 q0 = __floats2half2_rn(v0.x, v0.y);
                    __half2 q1 = __floats2half2_rn(v1.x, v1.y);
                    a[kc][1] = *(unsigned*)&q0; a[kc][3] = *(unsigned*)&q1;
                } else { a[kc][1] = 0u; a[kc][3] = 0u; }
            }
        } else {
            const __half2* plo = hin + (size_t)r_lo * 32;
            const __half2* phi = hin + (size_t)r_hi * 32;
#pragma unroll
            for (int kc = 0; kc < 4; kc++) {
                if (ok_lo) {
                    a[kc][0] = *(const unsigned*)&plo[kc * 8 + t];
                    a[kc][2] = *(const unsigned*)&plo[kc * 8 + t + 4];
                } else { a[kc][0] = 0u; a[kc][2] = 0u; }
                if (ok_hi) {
                    a[kc][1] = *(const unsigned*)&phi[kc * 8 + t];
                    a[kc][3] = *(const unsigned*)&phi[kc * 8 + t + 4];
                } else { a[kc][1] = 0u; a[kc][3] = 0u; }
            }
        }

        float c[8][4];
#pragma unroll
        for (int nt = 0; nt < 8; nt++) { c[nt][0]=0.f; c[nt][1]=0.f; c[nt][2]=0.f; c[nt][3]=0.f; }

#pragma unroll
        for (int kc = 0; kc < 4; kc++)
#pragma unroll
            for (int nt = 0; nt < 8; nt++) {
                uint2 bb = *(const uint2*)&bs[(((kc * 8 + nt) * 8 + g) * 4 + t) * 2];
                asm volatile(
                    "mma.sync.aligned.m16n8k16.row.col.f32.f16.f16.f32 "
                    "{%0,%1,%2,%3}, {%4,%5,%6,%7}, {%8,%9}, {%0,%1,%2,%3};"
                    : "+f"(c[nt][0]), "+f"(c[nt][1]), "+f"(c[nt][2]), "+f"(c[nt][3])
                    : "r"(a[kc][0]), "r"(a[kc][1]), "r"(a[kc][2]), "r"(a[kc][3]),
                      "r"(bb.x), "r"(bb.y));
            }

        if (ok_lo) {
            float dlo = rsqrtf((float)g_cnt[r_lo] + 1.0f);
            __half2* olo = g_g + (size_t)r_lo * 32;
#pragma unroll
            for (int nt = 0; nt < 8; nt++)
                olo[nt * 4 + t] = __floats2half2_rn(c[nt][0] * dlo, c[nt][1] * dlo);
        }
        if (ok_hi) {
            float dhi = rsqrtf((float)g_cnt[r_hi] + 1.0f);
            __half2* ohi = g_g + (size_t)r_hi * 32;
#pragma unroll
            for (int nt = 0; nt < 8; nt++)
                ohi[nt * 4 + t] = __floats2half2_rn(c[nt][2] * dhi, c[nt][3] * dhi);
        }
    }
}

// ---------------- aggregation: one warp per destination node ----------------
// agg is ALU/issue-bound (ncu: alu=36%, fma=24%, L2=23%, DRAM=6%): cut per-edge
// instructions. Groups of 4 gathers fold in fp16 (3 HADD2) then convert once
// to fp32 — ~40% fewer convert/add ops vs per-edge conversion.
__global__ __launch_bounds__(512) void agg_kernel(
    const float* __restrict__ bias,
    const int*   __restrict__ batch,
    int mode, int n)
{
    int w = (blockIdx.x * blockDim.x + threadIdx.x) >> 5;
    if (w >= n) return;
    int lane = threadIdx.x & 31;

    const char* gbase = (const char*)g_g + lane * 4;
#define LDG2(s) (*(const __half2*)(gbase + (size_t)((unsigned)(s) * 128u)))

    float2 acc = __half22float2(LDG2(w));    // self loop
    float2 acc2 = make_float2(0.f, 0.f);

    int cnt  = g_cnt[w];
    int cnum = min(cnt, CAP);
    const int* lst = &g_csr[(size_t)w * CAP];

    int e = 0;
    for (; e + 16 <= cnum; e += 16) {
        int4 sa = *(const int4*)&lst[e];
        int4 sb = *(const int4*)&lst[e + 4];
        int4 sc = *(const int4*)&lst[e + 8];
        int4 sd = *(const int4*)&lst[e + 12];
        __half2 h0 = LDG2(sa.x), h1 = LDG2(sa.y), h2 = LDG2(sa.z), h3 = LDG2(sa.w);
        __half2 h4 = LDG2(sb.x), h5 = LDG2(sb.y), h6 = LDG2(sb.z), h7 = LDG2(sb.w);
        __half2 h8 = LDG2(sc.x), h9 = LDG2(sc.y), ha = LDG2(sc.z), hb = LDG2(sc.w);
        __half2 hc = LDG2(sd.x), hd = LDG2(sd.y), he = LDG2(sd.z), hf = LDG2(sd.w);
        __half2 s0 = __hadd2(__hadd2(h0, h1), __hadd2(h2, h3));
        __half2 s1 = __hadd2(__hadd2(h4, h5), __hadd2(h6, h7));
        __half2 s2 = __hadd2(__hadd2(h8, h9), __hadd2(ha, hb));
        __half2 s3 = __hadd2(__hadd2(hc, hd), __hadd2(he, hf));
        float2 f0 = __half22float2(s0);
        float2 f1 = __half22float2(s1);
        float2 f2 = __half22float2(s2);
        float2 f3 = __half22float2(s3);
        acc.x  += f0.x + f1.x;  acc.y  += f0.y + f1.y;
        acc2.x += f2.x + f3.x;  acc2.y += f2.y + f3.y;
    }
    for (; e + 4 <= cnum; e += 4) {
        int4 sa = *(const int4*)&lst[e];
        __half2 s0 = __hadd2(__hadd2(LDG2(sa.x), LDG2(sa.y)),
                             __hadd2(LDG2(sa.z), LDG2(sa.w)));
        float2 f0 = __half22float2(s0);
        acc.x += f0.x;  acc.y += f0.y;
    }
    for (; e < cnum; e++) {
        float2 v = __half22float2(LDG2(lst[e]));
        acc.x += v.x;  acc.y += v.y;
    }
    acc.x += acc2.x;
    acc.y += acc2.y;
#undef LDG2

    float dv = rsqrtf((float)cnt + 1.0f);
    float2 bv = *(const float2*)&bias[lane * 2];
    float ox = fmaxf(fmaf(dv, acc.x, bv.x), 0.0f);
    float oy = fmaxf(fmaf(dv, acc.y, bv.y), 0.0f);

    if (mode == 1) {
        g_h1[(size_t)w * 32 + lane] = __floats2half2_rn(ox, oy);
    } else if (mode == 2) {
        g_h2[(size_t)w * 32 + lane] = __floats2half2_rn(ox, oy);
    } else {
        int b = batch[w];
        atomicAdd(&g_pool[b * 64 + lane * 2    ], ox);
        atomicAdd(&g_pool[b * 64 + lane * 2 + 1], oy);
    }
}

// ---------------- final: out[b][o] = mean-pool(b) . Wl[o] + bl[o] -----------
__global__ void final_kernel(const float* __restrict__ Wl,
                             const float* __restrict__ bl,
                             float* __restrict__ out)
{
    int t = blockIdx.x * blockDim.x + threadIdx.x;
    if (t >= BGR * 16) return;
    int b = t >> 4, o = t & 15;
    float inv = 1.0f / fmaxf((float)g_pcnt[b], 1.0f);
    const float* pr = &g_pool[b * 64];
    const float* wr = &Wl[o * 64];
    float s = 0.0f;
#pragma unroll
    for (int k = 0; k < 64; k++) s = fmaf(pr[k], wr[k], s);
    out[t] = fmaf(s, inv, bl[o]);
}

// ---------------- launch ----------------------------------------------------
extern "C" void kernel_launch(void* const* d_in, const int* in_sizes, int n_in,
                              void* d_out, int out_size)
{
    const float* x     = (const float*)d_in[0];
    const int*   ei    = (const int*)  d_in[1];
    const int*   batch = (const int*)  d_in[2];
    const float* W1    = (const float*)d_in[3];
    const float* b1    = (const float*)d_in[4];
    const float* W2    = (const float*)d_in[5];
    const float* b2    = (const float*)d_in[6];
    const float* W3    = (const float*)d_in[7];
    const float* b3    = (const float*)d_in[8];
    const float* Wl    = (const float*)d_in[9];
    const float* bl    = (const float*)d_in[10];
    float* out = (float*)d_out;

    int n = in_sizes[0] / 64;   // 50000
    int e = in_sizes[1] / 2;    // 1250000

    int nb_n = (n + 255) / 256;
    int nb_e = (e + 255) / 256;
    int nb_a = (n * 32 + 511) / 512;       // agg: 1 warp / node
    int ntiles = (n + 15) / 16;
    int nb_m = (ntiles + 7) / 8;           // gemm: 1 tile / warp (R8 config)

    // Launch order: zero(1), csr(2), gemm1(3), agg1(4) <- ncu window, pcnt(5).
    zero_kernel<<<nb_n, 256>>>(n);
    csr_build_kernel<<<nb_e, 256>>>(ei, e);

    gemm_mma_kernel<<<nb_m, 256>>>(x, 0, W1, n);
    agg_kernel<<<nb_a, 512>>>(b1, batch, 1, n);

    pcnt_kernel<<<nb_n, 256>>>(batch, n);

    gemm_mma_kernel<<<nb_m, 256>>>(x, 1, W2, n);
    agg_kernel<<<nb_a, 512>>>(b2, batch, 2, n);

    gemm_mma_kernel<<<nb_m, 256>>>(x, 2, W3, n);
    agg_kernel<<<nb_a, 512>>>(b3, batch, 3, n);

    final_kernel<<<(BGR * 16 + 255) / 256, 256>>>(Wl, bl, out);
}